// round 4
// baseline (speedup 1.0000x reference)
#include <cuda_runtime.h>
#include <math.h>

typedef unsigned long long ull;

#define HH 2048
#define WW 2048
#define NIMG 4
#define TOT (NIMG*HH*WW)
#define RANK0 8388607u

// harris tile geometry
#define TR 64
#define TC 32
#define GR 72            // TR+8 product rows
#define SXR 74           // TR+10 x rows
#define PX  43           // x pitch (floats, odd)
#define PIX2 41          // Ix/Iy packed pitch (ull, odd)
#define PSH 33           // smoothed pitch (odd)

#define SZ_IXY (GR*PIX2*8)           // 23616
#define OFF_B  SZ_IXY
#define SZ_S01 (GR*PSH*8)            // 19008
#define SZ_S2  (GR*PSH*4)            // 9504
#define SMEM_BYTES (SZ_IXY + SZ_S01 + SZ_S2)   // 52128
#define HARRIS_BLOCKS ((WW/TC)*(HH/TR)*NIMG)

// ---------------- f32x2 helpers ----------------
__device__ __forceinline__ ull pk2(float lo, float hi) {
    ull r; asm("mov.b64 %0,{%1,%2};" : "=l"(r) : "f"(lo), "f"(hi)); return r;
}
__device__ __forceinline__ void upk2(ull a, float& lo, float& hi) {
    asm("mov.b64 {%0,%1},%2;" : "=f"(lo), "=f"(hi) : "l"(a));
}
__device__ __forceinline__ ull fma2(ull a, ull b, ull c) {
    ull d; asm("fma.rn.f32x2 %0,%1,%2,%3;" : "=l"(d) : "l"(a), "l"(b), "l"(c)); return d;
}
__device__ __forceinline__ ull mul2(ull a, ull b) {
    ull d; asm("mul.rn.f32x2 %0,%1,%2;" : "=l"(d) : "l"(a), "l"(b)); return d;
}

// ---------------- device scratch ----------------
__device__ float    g_R[TOT];
__device__ unsigned g_hist[2048];
__device__ unsigned g_prefix, g_rank;
__device__ unsigned g_done1, g_done2, g_done3;
__device__ float    g_med;

// ---------------- shared select (one block) ----------------
__device__ __forceinline__ void select_pass(int shift, int nbits) {
    __shared__ unsigned ssum[256];
    const int nb = 1 << nbits;
    const int per = nb >> 8;
    const int t = threadIdx.x;
    unsigned pfx, rank;
    if (shift == 21) { pfx = 0u; rank = RANK0; }
    else             { pfx = g_prefix; rank = g_rank; }

    unsigned local[8];
    unsigned sum = 0;
    for (int i = 0; i < per; i++) { local[i] = g_hist[t*per + i]; sum += local[i]; }
    ssum[t] = sum;
    __syncthreads();
    unsigned run = sum;
    for (int d = 1; d < 256; d <<= 1) {
        unsigned add = (t >= d) ? ssum[t - d] : 0u;
        __syncthreads();
        run += add;
        ssum[t] = run;
        __syncthreads();
    }
    unsigned before = run - sum;
    if (rank >= before && rank < run) {
        unsigned cum = before;
        for (int i = 0; i < per; i++) {
            if (rank < cum + local[i]) {
                unsigned bin = (unsigned)(t*per + i);
                unsigned np = pfx | (bin << shift);
                g_prefix = np;
                g_rank = rank - cum;
                if (shift == 0) {
                    unsigned bb = (np & 0x80000000u) ? (np ^ 0x80000000u) : ~np;
                    g_med = __uint_as_float(bb);
                }
                break;
            }
            cum += local[i];
        }
    }
    __syncthreads();
    for (int i = t; i < nb; i += 256) g_hist[i] = 0;
}

// ---------------- fused Sobel + products + separable gauss + R + hist1 ----------------
__global__ __launch_bounds__(256, 3) void k_harris(const float* __restrict__ x,
                                                   const float* __restrict__ g2) {
    extern __shared__ __align__(16) unsigned char smraw[];
    ull*      sIxy  = (ull*)(smraw);
    float*    sX    = (float*)(smraw + OFF_B);
    ull*      sS01  = (ull*)(smraw + OFF_B);
    float*    sS2   = (float*)(smraw + OFF_B + SZ_S01);
    unsigned* shist = (unsigned*)(smraw);      // aliases sIxy in phase 4

    __shared__ float s_w[9];
    __shared__ unsigned s_last;

    const int t = threadIdx.x;
    const int n   = blockIdx.z;
    const int r0g = blockIdx.y * TR;
    const int c0g = blockIdx.x * TC;
    const float* __restrict__ xi = x + (size_t)n * HH * WW;

    if (t == 0) {
        double c = sqrt((double)g2[4*9 + 4]);
        for (int k = 0; k < 9; k++) s_w[k] = (float)((double)g2[4*9 + k] / c);
    }

    const bool interior = (blockIdx.x > 0) && (blockIdx.x < WW/TC - 1) &&
                          (blockIdx.y > 0) && (blockIdx.y < HH/TR - 1);

    // ---- phase 1: load x tile rows -5..68, cols -5..36 ----
    if (interior) {
        const float* base = xi + (size_t)(r0g - 5) * WW + (c0g - 5);
        for (int idx = t; idx < SXR*42; idx += 256) {
            int i = idx / 42, j = idx % 42;
            sX[i*PX + j] = base[(size_t)i * WW + j];
        }
    } else {
        for (int idx = t; idx < SXR*42; idx += 256) {
            int i = idx / 42, j = idx % 42;
            int gr = r0g + i - 5, gc = c0g + j - 5;
            float v = 0.f;
            if (gr >= 0 && gr < HH && gc >= 0 && gc < WW) v = xi[(size_t)gr * WW + gc];
            sX[i*PX + j] = v;
        }
    }
    __syncthreads();

    float w[9];
    #pragma unroll
    for (int k = 0; k < 9; k++) w[k] = s_w[k];
    ull w2[9];
    #pragma unroll
    for (int k = 0; k < 9; k++) w2[k] = pk2(w[k], w[k]);

    // ---- phase 2: Sobel -> packed (Ix,Iy); product rows 0..71, cols 0..39 ----
    for (int task = t; task < GR*4; task += 256) {
        int grp = task / GR;            // 0..3 -> 10 cols each
        int row = task % GR;
        int j0 = grp * 10;
        float ax[3][12];
        #pragma unroll
        for (int r = 0; r < 3; r++)
            #pragma unroll
            for (int c = 0; c < 12; c++)
                ax[r][c] = sX[(row + r)*PX + j0 + c];
        int gr = r0g + row - 4;
        bool rok = interior || (gr >= 0 && gr < HH);
        #pragma unroll
        for (int dj = 0; dj < 10; dj++) {
            float ix = 0.f, iy = 0.f;
            bool ok = rok && (interior || ((c0g + j0 + dj - 4) >= 0 && (c0g + j0 + dj - 4) < WW));
            if (ok) {
                ix = (ax[0][dj+2]-ax[0][dj]) + 2.f*(ax[1][dj+2]-ax[1][dj]) + (ax[2][dj+2]-ax[2][dj]);
                iy = (ax[2][dj]-ax[0][dj])   + 2.f*(ax[2][dj+1]-ax[0][dj+1]) + (ax[2][dj+2]-ax[0][dj+2]);
            }
            sIxy[row*PIX2 + j0 + dj] = pk2(ix, iy);
        }
    }
    __syncthreads();

    // ---- phase 3: horizontal gauss; packed (Sxx,Syy) + scalar Sxy ----
    for (int task = t; task < GR*4; task += 256) {
        int grp = task / GR;            // 0..3 -> 8 out cols each
        int row = task % GR;
        int o0 = grp * 8;
        ull   q01[16];
        float qxy[16];
        #pragma unroll
        for (int k = 0; k < 16; k++) {
            ull p = sIxy[row*PIX2 + o0 + k];
            float fx, fy; upk2(p, fx, fy);
            q01[k] = mul2(p, p);
            qxy[k] = fx * fy;
        }
        #pragma unroll
        for (int o = 0; o < 8; o++) {
            ull acc2 = 0ull;
            float accs = 0.f;
            #pragma unroll
            for (int k = 0; k < 9; k++) {
                acc2 = fma2(w2[k], q01[o + k], acc2);
                accs = fmaf(w[k], qxy[o + k], accs);
            }
            sS01[row*PSH + o0 + o] = acc2;
            sS2 [row*PSH + o0 + o] = accs;
        }
    }
    __syncthreads();

    for (int i = t; i < 2048; i += 256) shist[i] = 0;
    __syncthreads();

    // ---- phase 4: vertical gauss + R + histogram ----
    {
        const int col = t & 31;
        const int r0l = (t >> 5) * 8;
        const unsigned lane = t & 31;
        ull   win01[16];
        float win2[16];
        #pragma unroll
        for (int k = 0; k < 16; k++) {
            win01[k] = sS01[(r0l + k)*PSH + col];
            win2[k]  = sS2 [(r0l + k)*PSH + col];
        }
        size_t obase = (size_t)n * HH * WW + (size_t)(r0g + r0l) * WW + (c0g + col);
        #pragma unroll
        for (int o = 0; o < 8; o++) {
            ull acc2 = 0ull;
            float s2 = 0.f;
            #pragma unroll
            for (int k = 0; k < 9; k++) {
                acc2 = fma2(w2[k], win01[o + k], acc2);
                s2   = fmaf(w[k], win2[o + k], s2);
            }
            float s0, s1; upk2(acc2, s0, s1);
            float det = s0*s1 - s2*s2;
            float tr  = s0 + s1;
            float R   = det - 0.05f*tr*tr;
            g_R[obase + (size_t)o * WW] = R;

            unsigned b = __float_as_uint(R);
            unsigned u = b ^ ((b & 0x80000000u) ? 0xFFFFFFFFu : 0x80000000u);
            unsigned bin = u >> 21;
            unsigned peers = __match_any_sync(0xFFFFFFFFu, bin);
            if ((unsigned)(__ffs(peers) - 1) == lane)
                atomicAdd(&shist[bin], (unsigned)__popc(peers));
        }
    }
    __syncthreads();

    for (int i = t; i < 2048; i += 256) {
        unsigned c = shist[i];
        if (c) atomicAdd(&g_hist[i], c);
    }
    __threadfence();
    if (t == 0) s_last = (atomicAdd(&g_done1, 1) == HARRIS_BLOCKS - 1) ? 1u : 0u;
    __syncthreads();
    if (s_last) {
        __threadfence();
        select_pass(21, 11);
        if (t == 0) g_done1 = 0;
    }
}

// ---------------- pass 2: full scan, hist bits 20..10, fused select ----------------
__global__ __launch_bounds__(256) void k_hist2() {
    __shared__ unsigned s_hist[2048];
    __shared__ unsigned s_last;
    for (int i = threadIdx.x; i < 2048; i += 256) s_hist[i] = 0;
    __syncthreads();

    const unsigned pfx_hi = g_prefix >> 21;
    const unsigned lane = threadIdx.x & 31;
    const float4* __restrict__ Rv = (const float4*)g_R;
    const size_t n4 = TOT / 4;
    const size_t stride = (size_t)gridDim.x * 256;

    for (size_t i4 = (size_t)blockIdx.x * 256 + threadIdx.x; i4 < n4; i4 += stride) {
        float4 v = Rv[i4];
        float vals[4] = {v.x, v.y, v.z, v.w};
        #pragma unroll
        for (int e = 0; e < 4; e++) {
            unsigned b = __float_as_uint(vals[e]);
            unsigned u = b ^ ((b & 0x80000000u) ? 0xFFFFFFFFu : 0x80000000u);
            bool match = ((u >> 21) == pfx_hi);
            unsigned bin = (u >> 10) & 2047u;
            unsigned bal = __ballot_sync(0xFFFFFFFFu, match);
            if (match) {
                unsigned peers = __match_any_sync(bal, bin);
                if ((unsigned)(__ffs(peers) - 1) == lane)
                    atomicAdd(&s_hist[bin], (unsigned)__popc(peers));
            }
        }
    }
    __syncthreads();
    for (int i = threadIdx.x; i < 2048; i += 256) {
        unsigned c = s_hist[i];
        if (c) atomicAdd(&g_hist[i], c);
    }
    __threadfence();
    if (threadIdx.x == 0) s_last = (atomicAdd(&g_done2, 1) == gridDim.x - 1) ? 1u : 0u;
    __syncthreads();
    if (s_last) {
        __threadfence();
        select_pass(10, 11);
        if (threadIdx.x == 0) g_done2 = 0;
    }
}

// ---------------- pass 3: full scan, hist bits 9..0, fused select ----------------
__global__ __launch_bounds__(256) void k_hist3() {
    __shared__ unsigned s_hist[1024];
    __shared__ unsigned s_last;
    for (int i = threadIdx.x; i < 1024; i += 256) s_hist[i] = 0;
    __syncthreads();

    const unsigned pfx = g_prefix >> 10;
    const unsigned lane = threadIdx.x & 31;
    const float4* __restrict__ Rv = (const float4*)g_R;
    const size_t n4 = TOT / 4;
    const size_t stride = (size_t)gridDim.x * 256;

    for (size_t i4 = (size_t)blockIdx.x * 256 + threadIdx.x; i4 < n4; i4 += stride) {
        float4 v = Rv[i4];
        float vals[4] = {v.x, v.y, v.z, v.w};
        #pragma unroll
        for (int e = 0; e < 4; e++) {
            unsigned b = __float_as_uint(vals[e]);
            unsigned u = b ^ ((b & 0x80000000u) ? 0xFFFFFFFFu : 0x80000000u);
            bool match = ((u >> 10) == pfx);
            unsigned bin = u & 1023u;
            unsigned bal = __ballot_sync(0xFFFFFFFFu, match);
            if (match) {
                unsigned peers = __match_any_sync(bal, bin);
                if ((unsigned)(__ffs(peers) - 1) == lane)
                    atomicAdd(&s_hist[bin], (unsigned)__popc(peers));
            }
        }
    }
    __syncthreads();
    for (int i = threadIdx.x; i < 1024; i += 256) {
        unsigned c = s_hist[i];
        if (c) atomicAdd(&g_hist[i], c);
    }
    __threadfence();
    if (threadIdx.x == 0) s_last = (atomicAdd(&g_done3, 1) == gridDim.x - 1) ? 1u : 0u;
    __syncthreads();
    if (s_last) {
        __threadfence();
        select_pass(0, 10);
        if (threadIdx.x == 0) g_done3 = 0;
    }
}

// ---------------- threshold + 7x7 NMS: prefix/suffix max both axes ----------------
#define PTX 39   // sxt pitch (odd)
#define PTM 33   // hmax pitch (odd)
__global__ __launch_bounds__(256) void k_pool(float* __restrict__ out) {
    __shared__ float sxt[70*PTX];
    __shared__ float shm[70*PTM];
    const int bx = blockIdx.x, by = blockIdx.y, n = blockIdx.z;
    const int r0 = by * 64, c0 = bx * 32;
    const float* __restrict__ Ri = g_R + (size_t)n * HH * WW;
    const float med = g_med;
    const float NEG_INF = __int_as_float(0xFF800000);
    const int t = threadIdx.x;

    const bool interior = (bx > 0) && (bx < WW/32 - 1) && (by > 0) && (by < HH/64 - 1);

    // phase 1: load + threshold, rows -3..66, cols -3..34
    if (interior) {
        const float* base = Ri + (size_t)(r0 - 3) * WW + (c0 - 3);
        for (int idx = t; idx < 70*38; idx += 256) {
            int i = idx / 38, j = idx % 38;
            float R = base[(size_t)i * WW + j];
            sxt[i*PTX + j] = (R > med) ? R : 0.f;
        }
    } else {
        for (int idx = t; idx < 70*38; idx += 256) {
            int i = idx / 38, j = idx % 38;
            int gr = r0 + i - 3, gc = c0 + j - 3;
            float v = NEG_INF;
            if (gr >= 0 && gr < HH && gc >= 0 && gc < WW) {
                float R = Ri[(size_t)gr * WW + gc];
                v = (R > med) ? R : 0.f;
            }
            sxt[i*PTX + j] = v;
        }
    }
    __syncthreads();

    // phase 2: horizontal 7-max via prefix/suffix, 8 outputs/task
    for (int task = t; task < 70*4; task += 256) {
        int grp = task / 70;
        int row = task % 70;
        int j0 = grp * 8;
        float v[14];
        #pragma unroll
        for (int k = 0; k < 14; k++) v[k] = sxt[row*PTX + j0 + k];
        float suf[7], pre[7];
        suf[6] = v[6];
        #pragma unroll
        for (int i = 5; i >= 0; i--) suf[i] = fmaxf(v[i], suf[i+1]);
        pre[0] = v[7];
        #pragma unroll
        for (int i = 1; i < 7; i++) pre[i] = fmaxf(pre[i-1], v[7+i]);
        #pragma unroll
        for (int o = 0; o < 8; o++) {
            float m = (o == 0) ? suf[0] : ((o == 7) ? pre[6] : fmaxf(suf[o], pre[o-1]));
            shm[row*PTM + j0 + o] = m;
        }
    }
    __syncthreads();

    // phase 3: vertical 7-max via prefix/suffix, 8 outputs/thread
    {
        const int col = t & 31;
        const int r0l = (t >> 5) * 8;
        float v[14];
        #pragma unroll
        for (int k = 0; k < 14; k++) v[k] = shm[(r0l + k)*PTM + col];
        float suf[7], pre[7];
        suf[6] = v[6];
        #pragma unroll
        for (int i = 5; i >= 0; i--) suf[i] = fmaxf(v[i], suf[i+1]);
        pre[0] = v[7];
        #pragma unroll
        for (int i = 1; i < 7; i++) pre[i] = fmaxf(pre[i-1], v[7+i]);

        size_t obase = (size_t)n * HH * WW + (size_t)(r0 + r0l) * WW + (c0 + col);
        #pragma unroll
        for (int o = 0; o < 8; o++) {
            float m = (o == 0) ? suf[0] : ((o == 7) ? pre[6] : fmaxf(suf[o], pre[o-1]));
            float xt = sxt[(r0l + o + 3)*PTX + col + 3];
            out[obase + (size_t)o * WW] = (xt == m) ? xt : 0.f;
        }
    }
}

// ---------------- launch ----------------
extern "C" void kernel_launch(void* const* d_in, const int* in_sizes, int n_in,
                              void* d_out, int out_size) {
    const float* x     = (const float*)d_in[0];
    const float* gauss = (const float*)d_in[2];
    float* out = (float*)d_out;

    static int configured = 0;
    if (!configured) {
        cudaFuncSetAttribute(k_harris, cudaFuncAttributeMaxDynamicSharedMemorySize, SMEM_BYTES);
        cudaFuncSetAttribute(k_harris, cudaFuncAttributePreferredSharedMemoryCarveout, 100);
        configured = 1;
    }

    dim3 gh(WW/TC, HH/TR, NIMG);
    k_harris<<<gh, 256, SMEM_BYTES>>>(x, gauss);

    k_hist2<<<2048, 256>>>();
    k_hist3<<<2048, 256>>>();

    dim3 gp(WW/32, HH/64, NIMG);
    k_pool<<<gp, 256>>>(out);
}

// round 5
// speedup vs baseline: 1.1079x; 1.1079x over previous
#include <cuda_runtime.h>
#include <math.h>

#define HH 2048
#define WW 2048
#define NIMG 4
#define TOT (NIMG*HH*WW)
#define RANK0 8388607u   // (TOT-1)/2

// harris tile geometry (32x32 output tile -> high occupancy)
#define TR 32
#define TC 32
#define GR 40            // TR+8
#define SXR 42           // TR+10
#define SXC 42           // used x cols
#define PX  43           // x pitch (odd)
#define PIX 41           // Ix/Iy pitch (odd)
#define PSH 33           // smoothed pitch (odd)
#define SIXY (GR*PIX)              // 1640 floats
#define SHCH (GR*PSH)              // 1320 floats per channel
#define SC_FLOATS (3*SHCH)         // 3960 (>= 42*43=1806 for x overlay)
#define SMEM_FLOATS (2*SIXY + SC_FLOATS)   // 7240
#define SMEM_BYTES (SMEM_FLOATS*4)         // 28960
#define HARRIS_BLOCKS ((WW/TC)*(HH/TR)*NIMG)  // 64*64*4 = 16384

// ---------------- device scratch ----------------
__device__ float    g_R[TOT];
__device__ unsigned g_hist[2048];
__device__ unsigned g_prefix, g_rank;
__device__ unsigned g_done1, g_done2, g_done3;
__device__ float    g_med;

// ---------------- shared select (one block, 256 threads) ----------------
__device__ __forceinline__ void select_pass(int shift, int nbits) {
    __shared__ unsigned ssum[256];
    const int nb = 1 << nbits;
    const int per = nb >> 8;
    const int t = threadIdx.x;
    unsigned pfx, rank;
    if (shift == 21) { pfx = 0u; rank = RANK0; }
    else             { pfx = g_prefix; rank = g_rank; }

    unsigned local[8];
    unsigned sum = 0;
    for (int i = 0; i < per; i++) { local[i] = g_hist[t*per + i]; sum += local[i]; }
    ssum[t] = sum;
    __syncthreads();
    unsigned run = sum;
    for (int d = 1; d < 256; d <<= 1) {
        unsigned add = (t >= d) ? ssum[t - d] : 0u;
        __syncthreads();
        run += add;
        ssum[t] = run;
        __syncthreads();
    }
    unsigned before = run - sum;
    if (rank >= before && rank < run) {
        unsigned cum = before;
        for (int i = 0; i < per; i++) {
            if (rank < cum + local[i]) {
                unsigned bin = (unsigned)(t*per + i);
                unsigned np = pfx | (bin << shift);
                g_prefix = np;
                g_rank = rank - cum;
                if (shift == 0) {
                    unsigned bb = (np & 0x80000000u) ? (np ^ 0x80000000u) : ~np;
                    g_med = __uint_as_float(bb);
                }
                break;
            }
            cum += local[i];
        }
    }
    __syncthreads();
    for (int i = t; i < nb; i += 256) g_hist[i] = 0;
}

// ---------------- fused Sobel + products + separable gauss + R + hist1 ----------------
__global__ __launch_bounds__(256) void k_harris(const float* __restrict__ x,
                                                const float* __restrict__ g2) {
    extern __shared__ float smem[];
    float* sIx = smem;                 // GR x PIX
    float* sIy = smem + SIXY;
    float* sC  = smem + 2*SIXY;        // union: x tile (SXR*PX) then sh[3] (GR*PSH each)
    unsigned* shist = (unsigned*)smem; // aliases sIx/sIy in phase 4 (2048 <= 2*SIXY)

    __shared__ float s_w[9];
    __shared__ unsigned s_last;

    const int t = threadIdx.x;
    const int n   = blockIdx.z;
    const int r0g = blockIdx.y * TR;
    const int c0g = blockIdx.x * TC;
    const float* __restrict__ xi = x + (size_t)n * HH * WW;

    if (t == 0) {
        double c = sqrt((double)g2[4*9 + 4]);
        for (int k = 0; k < 9; k++) s_w[k] = (float)((double)g2[4*9 + k] / c);
    }

    const bool interior = (blockIdx.x > 0) && (blockIdx.x < WW/TC - 1) &&
                          (blockIdx.y > 0) && (blockIdx.y < HH/TR - 1);

    // ---- phase 1: load x tile rows -5..36, cols -5..36 ----
    if (interior) {
        const float* base = xi + (size_t)(r0g - 5) * WW + (c0g - 5);
        for (int idx = t; idx < SXR*SXC; idx += 256) {
            int i = idx / SXC, j = idx % SXC;
            sC[i*PX + j] = base[(size_t)i * WW + j];
        }
    } else {
        for (int idx = t; idx < SXR*SXC; idx += 256) {
            int i = idx / SXC, j = idx % SXC;
            int gr = r0g + i - 5, gc = c0g + j - 5;
            float v = 0.f;
            if (gr >= 0 && gr < HH && gc >= 0 && gc < WW) v = xi[(size_t)gr * WW + gc];
            sC[i*PX + j] = v;
        }
    }
    __syncthreads();

    float w[9];
    #pragma unroll
    for (int k = 0; k < 9; k++) w[k] = s_w[k];

    // ---- phase 2: sobel Ix,Iy at rel rows -4..35, rel cols -4..35 ----
    for (int task = t; task < GR*10; task += 256) {
        int i  = task / 10;
        int j0 = (task % 10) * 4;
        float a[3][6];
        #pragma unroll
        for (int r = 0; r < 3; r++)
            #pragma unroll
            for (int c = 0; c < 6; c++)
                a[r][c] = sC[(i + r)*PX + j0 + c];
        if (interior) {
            #pragma unroll
            for (int dj = 0; dj < 4; dj++) {
                float ix = (a[0][dj+2]-a[0][dj]) + 2.f*(a[1][dj+2]-a[1][dj]) + (a[2][dj+2]-a[2][dj]);
                float iy = (a[2][dj]-a[0][dj])   + 2.f*(a[2][dj+1]-a[0][dj+1]) + (a[2][dj+2]-a[0][dj+2]);
                sIx[i*PIX + j0 + dj] = ix;
                sIy[i*PIX + j0 + dj] = iy;
            }
        } else {
            int gr = r0g + i - 4;
            bool rok = (gr >= 0 && gr < HH);
            #pragma unroll
            for (int dj = 0; dj < 4; dj++) {
                int gc = c0g + j0 + dj - 4;
                float ix = 0.f, iy = 0.f;
                if (rok && gc >= 0 && gc < WW) {
                    ix = (a[0][dj+2]-a[0][dj]) + 2.f*(a[1][dj+2]-a[1][dj]) + (a[2][dj+2]-a[2][dj]);
                    iy = (a[2][dj]-a[0][dj])   + 2.f*(a[2][dj+1]-a[0][dj+1]) + (a[2][dj+2]-a[0][dj+2]);
                }
                sIx[i*PIX + j0 + dj] = ix;
                sIy[i*PIX + j0 + dj] = iy;
            }
        }
    }
    __syncthreads();

    // ---- phase 3: horizontal gauss of products (products on the fly) ----
    for (int task = t; task < GR*8; task += 256) {
        int row = task >> 3;
        int j0  = (task & 7) << 2;
        const float* bx = &sIx[row*PIX + j0];
        const float* by = &sIy[row*PIX + j0];
        float ix[12], iy[12];
        #pragma unroll
        for (int p = 0; p < 12; p++) { ix[p] = bx[p]; iy[p] = by[p]; }
        float s0[4] = {0,0,0,0}, s1[4] = {0,0,0,0}, s2[4] = {0,0,0,0};
        #pragma unroll
        for (int p = 0; p < 12; p++) {
            float pxx = ix[p]*ix[p];
            float pyy = iy[p]*iy[p];
            float pxy = ix[p]*iy[p];
            #pragma unroll
            for (int j = 0; j < 4; j++) {
                if (p - j >= 0 && p - j <= 8) {
                    float wk = w[p - j];
                    s0[j] += wk*pxx;
                    s1[j] += wk*pyy;
                    s2[j] += wk*pxy;
                }
            }
        }
        #pragma unroll
        for (int j = 0; j < 4; j++) {
            sC[0*SHCH + row*PSH + j0 + j] = s0[j];
            sC[1*SHCH + row*PSH + j0 + j] = s1[j];
            sC[2*SHCH + row*PSH + j0 + j] = s2[j];
        }
    }
    __syncthreads();

    for (int i = t; i < 2048; i += 256) shist[i] = 0;
    __syncthreads();

    // ---- phase 4: vertical gauss + R + histogram (4 rows/thread) ----
    {
        const int col = t & 31;
        const int r0l = (t >> 5) * 4;
        const unsigned lane = t & 31;
        float win[12], s0[4], s1[4];

        #pragma unroll
        for (int k = 0; k < 12; k++) win[k] = sC[0*SHCH + (r0l + k)*PSH + col];
        #pragma unroll
        for (int o = 0; o < 4; o++) {
            float s = 0.f;
            #pragma unroll
            for (int k = 0; k < 9; k++) s += w[k]*win[o + k];
            s0[o] = s;
        }
        #pragma unroll
        for (int k = 0; k < 12; k++) win[k] = sC[1*SHCH + (r0l + k)*PSH + col];
        #pragma unroll
        for (int o = 0; o < 4; o++) {
            float s = 0.f;
            #pragma unroll
            for (int k = 0; k < 9; k++) s += w[k]*win[o + k];
            s1[o] = s;
        }
        #pragma unroll
        for (int k = 0; k < 12; k++) win[k] = sC[2*SHCH + (r0l + k)*PSH + col];

        size_t obase = (size_t)n * HH * WW + (size_t)(r0g + r0l) * WW + (c0g + col);
        #pragma unroll
        for (int o = 0; o < 4; o++) {
            float s2 = 0.f;
            #pragma unroll
            for (int k = 0; k < 9; k++) s2 += w[k]*win[o + k];
            float det = s0[o]*s1[o] - s2*s2;
            float tr  = s0[o] + s1[o];
            float R   = det - 0.05f*tr*tr;
            g_R[obase + (size_t)o * WW] = R;

            unsigned b = __float_as_uint(R);
            unsigned u = b ^ ((b & 0x80000000u) ? 0xFFFFFFFFu : 0x80000000u);
            unsigned bin = u >> 21;
            unsigned peers = __match_any_sync(0xFFFFFFFFu, bin);
            if ((unsigned)(__ffs(peers) - 1) == lane)
                atomicAdd(&shist[bin], (unsigned)__popc(peers));
        }
    }
    __syncthreads();

    for (int i = t; i < 2048; i += 256) {
        unsigned c = shist[i];
        if (c) atomicAdd(&g_hist[i], c);
    }
    __threadfence();
    if (t == 0) s_last = (atomicAdd(&g_done1, 1) == HARRIS_BLOCKS - 1) ? 1u : 0u;
    __syncthreads();
    if (s_last) {
        __threadfence();
        select_pass(21, 11);
        if (t == 0) g_done1 = 0;
    }
}

// ---------------- pass 2: full scan, match top-11, hist bits 20..10, fused select ----------------
__global__ __launch_bounds__(256) void k_hist2() {
    __shared__ unsigned s_hist[2048];
    __shared__ unsigned s_last;
    for (int i = threadIdx.x; i < 2048; i += 256) s_hist[i] = 0;
    __syncthreads();

    const unsigned pfx_hi = g_prefix >> 21;
    const unsigned lane = threadIdx.x & 31;
    const float4* __restrict__ Rv = (const float4*)g_R;
    const size_t n4 = TOT / 4;
    const size_t stride = (size_t)gridDim.x * 256;

    for (size_t i4 = (size_t)blockIdx.x * 256 + threadIdx.x; i4 < n4; i4 += stride) {
        float4 v = Rv[i4];
        float vals[4] = {v.x, v.y, v.z, v.w};
        #pragma unroll
        for (int e = 0; e < 4; e++) {
            unsigned b = __float_as_uint(vals[e]);
            unsigned u = b ^ ((b & 0x80000000u) ? 0xFFFFFFFFu : 0x80000000u);
            bool match = ((u >> 21) == pfx_hi);
            unsigned bin = (u >> 10) & 2047u;
            unsigned bal = __ballot_sync(0xFFFFFFFFu, match);
            if (match) {
                unsigned peers = __match_any_sync(bal, bin);
                if ((unsigned)(__ffs(peers) - 1) == lane)
                    atomicAdd(&s_hist[bin], (unsigned)__popc(peers));
            }
        }
    }
    __syncthreads();
    for (int i = threadIdx.x; i < 2048; i += 256) {
        unsigned c = s_hist[i];
        if (c) atomicAdd(&g_hist[i], c);
    }
    __threadfence();
    if (threadIdx.x == 0) s_last = (atomicAdd(&g_done2, 1) == gridDim.x - 1) ? 1u : 0u;
    __syncthreads();
    if (s_last) {
        __threadfence();
        select_pass(10, 11);
        if (threadIdx.x == 0) g_done2 = 0;
    }
}

// ---------------- pass 3: full scan, match top-22, hist bits 9..0, fused select ----------------
__global__ __launch_bounds__(256) void k_hist3() {
    __shared__ unsigned s_hist[1024];
    __shared__ unsigned s_last;
    for (int i = threadIdx.x; i < 1024; i += 256) s_hist[i] = 0;
    __syncthreads();

    const unsigned pfx = g_prefix >> 10;
    const unsigned lane = threadIdx.x & 31;
    const float4* __restrict__ Rv = (const float4*)g_R;
    const size_t n4 = TOT / 4;
    const size_t stride = (size_t)gridDim.x * 256;

    for (size_t i4 = (size_t)blockIdx.x * 256 + threadIdx.x; i4 < n4; i4 += stride) {
        float4 v = Rv[i4];
        float vals[4] = {v.x, v.y, v.z, v.w};
        #pragma unroll
        for (int e = 0; e < 4; e++) {
            unsigned b = __float_as_uint(vals[e]);
            unsigned u = b ^ ((b & 0x80000000u) ? 0xFFFFFFFFu : 0x80000000u);
            bool match = ((u >> 10) == pfx);
            unsigned bin = u & 1023u;
            unsigned bal = __ballot_sync(0xFFFFFFFFu, match);
            if (match) {
                unsigned peers = __match_any_sync(bal, bin);
                if ((unsigned)(__ffs(peers) - 1) == lane)
                    atomicAdd(&s_hist[bin], (unsigned)__popc(peers));
            }
        }
    }
    __syncthreads();
    for (int i = threadIdx.x; i < 1024; i += 256) {
        unsigned c = s_hist[i];
        if (c) atomicAdd(&g_hist[i], c);
    }
    __threadfence();
    if (threadIdx.x == 0) s_last = (atomicAdd(&g_done3, 1) == gridDim.x - 1) ? 1u : 0u;
    __syncthreads();
    if (s_last) {
        __threadfence();
        select_pass(0, 10);
        if (threadIdx.x == 0) g_done3 = 0;
    }
}

// ---------------- threshold + 7x7 NMS: prefix/suffix max both axes ----------------
#define PTX 39   // sxt pitch (odd)
#define PTM 33   // hmax pitch (odd)
__global__ __launch_bounds__(256) void k_pool(float* __restrict__ out) {
    __shared__ float sxt[70*PTX];
    __shared__ float shm[70*PTM];
    const int bx = blockIdx.x, by = blockIdx.y, n = blockIdx.z;
    const int r0 = by * 64, c0 = bx * 32;
    const float* __restrict__ Ri = g_R + (size_t)n * HH * WW;
    const float med = g_med;
    const float NEG_INF = __int_as_float(0xFF800000);
    const int t = threadIdx.x;

    const bool interior = (bx > 0) && (bx < WW/32 - 1) && (by > 0) && (by < HH/64 - 1);

    // phase 1: load + threshold, rows -3..66, cols -3..34
    if (interior) {
        const float* base = Ri + (size_t)(r0 - 3) * WW + (c0 - 3);
        for (int idx = t; idx < 70*38; idx += 256) {
            int i = idx / 38, j = idx % 38;
            float R = base[(size_t)i * WW + j];
            sxt[i*PTX + j] = (R > med) ? R : 0.f;
        }
    } else {
        for (int idx = t; idx < 70*38; idx += 256) {
            int i = idx / 38, j = idx % 38;
            int gr = r0 + i - 3, gc = c0 + j - 3;
            float v = NEG_INF;
            if (gr >= 0 && gr < HH && gc >= 0 && gc < WW) {
                float R = Ri[(size_t)gr * WW + gc];
                v = (R > med) ? R : 0.f;
            }
            sxt[i*PTX + j] = v;
        }
    }
    __syncthreads();

    // phase 2: horizontal 7-max via prefix/suffix, 8 outputs/task
    for (int task = t; task < 70*4; task += 256) {
        int grp = task / 70;
        int row = task % 70;
        int j0 = grp * 8;
        float v[14];
        #pragma unroll
        for (int k = 0; k < 14; k++) v[k] = sxt[row*PTX + j0 + k];
        float suf[7], pre[7];
        suf[6] = v[6];
        #pragma unroll
        for (int i = 5; i >= 0; i--) suf[i] = fmaxf(v[i], suf[i+1]);
        pre[0] = v[7];
        #pragma unroll
        for (int i = 1; i < 7; i++) pre[i] = fmaxf(pre[i-1], v[7+i]);
        #pragma unroll
        for (int o = 0; o < 8; o++) {
            float m = (o == 0) ? suf[0] : ((o == 7) ? pre[6] : fmaxf(suf[o], pre[o-1]));
            shm[row*PTM + j0 + o] = m;
        }
    }
    __syncthreads();

    // phase 3: vertical 7-max via prefix/suffix, 8 outputs/thread
    {
        const int col = t & 31;
        const int r0l = (t >> 5) * 8;
        float v[14];
        #pragma unroll
        for (int k = 0; k < 14; k++) v[k] = shm[(r0l + k)*PTM + col];
        float suf[7], pre[7];
        suf[6] = v[6];
        #pragma unroll
        for (int i = 5; i >= 0; i--) suf[i] = fmaxf(v[i], suf[i+1]);
        pre[0] = v[7];
        #pragma unroll
        for (int i = 1; i < 7; i++) pre[i] = fmaxf(pre[i-1], v[7+i]);

        size_t obase = (size_t)n * HH * WW + (size_t)(r0 + r0l) * WW + (c0 + col);
        #pragma unroll
        for (int o = 0; o < 8; o++) {
            float m = (o == 0) ? suf[0] : ((o == 7) ? pre[6] : fmaxf(suf[o], pre[o-1]));
            float xt = sxt[(r0l + o + 3)*PTX + col + 3];
            out[obase + (size_t)o * WW] = (xt == m) ? xt : 0.f;
        }
    }
}

// ---------------- launch ----------------
extern "C" void kernel_launch(void* const* d_in, const int* in_sizes, int n_in,
                              void* d_out, int out_size) {
    const float* x     = (const float*)d_in[0];
    const float* gauss = (const float*)d_in[2];
    float* out = (float*)d_out;

    static int configured = 0;
    if (!configured) {
        cudaFuncSetAttribute(k_harris, cudaFuncAttributeMaxDynamicSharedMemorySize, SMEM_BYTES);
        cudaFuncSetAttribute(k_harris, cudaFuncAttributePreferredSharedMemoryCarveout, 100);
        configured = 1;
    }

    dim3 gh(WW/TC, HH/TR, NIMG);      // 64 x 64 x 4
    k_harris<<<gh, 256, SMEM_BYTES>>>(x, gauss);

    k_hist2<<<2048, 256>>>();
    k_hist3<<<2048, 256>>>();

    dim3 gp(WW/32, HH/64, NIMG);
    k_pool<<<gp, 256>>>(out);
}